// round 6
// baseline (speedup 1.0000x reference)
#include <cuda_runtime.h>
#include <cuda_fp16.h>
#include <cstdint>

#define D 64
#define MAXN 100000
#define MAXE 1600000
#define SCAN_BLK 1024

// Scratch (device globals — no allocation allowed)
__device__ float g_agg[MAXN * D];      // agg result; later reused as t2
__device__ float g_t1[MAXN * D];       // output of first Linear
__device__ float g_stats[256];         // sum1[64], sq1[64], sum2[64], sq2[64]
__device__ uint2 g_xh[MAXN * 16];      // x staged as fp16 (64 halfs/row)
__device__ int   g_cnt[MAXN + SCAN_BLK];
__device__ int   g_start[MAXN + 1];
__device__ int   g_cursor[MAXN];
__device__ int   g_srcs[MAXE];
__device__ int   g_bsum[SCAN_BLK];

// ---------------------------------------------------------------------------
// K_prep: stage x as fp16, zero stats + degree counters, set g_start[N]=E
// ---------------------------------------------------------------------------
__global__ __launch_bounds__(256) void k_prep(const float* __restrict__ x,
                                              int N, int E) {
    int i = blockIdx.x * 256 + threadIdx.x;
    if (i < 256) g_stats[i] = 0.f;
    if (i < N + SCAN_BLK) g_cnt[i] = 0;
    if (i == 0) g_start[N] = E;
    int n4 = N * 16;
    if (i >= n4) return;
    float4 v = ((const float4*)x)[i];
    __half2 h0 = __floats2half2_rn(v.x, v.y);
    __half2 h1 = __floats2half2_rn(v.z, v.w);
    uint2 u;
    u.x = *(unsigned*)&h0;
    u.y = *(unsigned*)&h1;
    g_xh[i] = u;
}

__global__ __launch_bounds__(256) void k_hist(const int* __restrict__ ei, int E) {
    int e = blockIdx.x * 256 + threadIdx.x;
    if (e >= E) return;
    atomicAdd(&g_cnt[ei[E + e]], 1);
}

__device__ __forceinline__ int block_scan_1024(int v, int* warpsum, int* total) {
    int lane = threadIdx.x & 31, wid = threadIdx.x >> 5;
    int inc = v;
    #pragma unroll
    for (int o = 1; o < 32; o <<= 1) {
        int u = __shfl_up_sync(0xFFFFFFFFu, inc, o);
        if (lane >= o) inc += u;
    }
    if (lane == 31) warpsum[wid] = inc;
    __syncthreads();
    if (wid == 0) {
        int w = warpsum[lane];
        #pragma unroll
        for (int o = 1; o < 32; o <<= 1) {
            int u = __shfl_up_sync(0xFFFFFFFFu, w, o);
            if (lane >= o) w += u;
        }
        warpsum[lane] = w;
    }
    __syncthreads();
    int base = (wid > 0) ? warpsum[wid - 1] : 0;
    *total = warpsum[31];
    return inc + base;
}

__global__ __launch_bounds__(SCAN_BLK) void k_scan1(int N) {
    __shared__ int warpsum[32];
    int gi = blockIdx.x * SCAN_BLK + threadIdx.x;
    int v = (gi < N) ? g_cnt[gi] : 0;
    int total;
    int incl = block_scan_1024(v, warpsum, &total);
    if (gi < N) {
        g_cnt[gi] = incl;
        g_start[gi] = incl - v;
    }
    if (threadIdx.x == SCAN_BLK - 1) g_bsum[blockIdx.x] = total;
}

__global__ __launch_bounds__(SCAN_BLK) void k_scan2(int nb) {
    __shared__ int warpsum[32];
    int t = threadIdx.x;
    int v = (t < nb) ? g_bsum[t] : 0;
    int total;
    int incl = block_scan_1024(v, warpsum, &total);
    if (t < nb) g_bsum[t] = incl - v;
}

__global__ __launch_bounds__(256) void k_scan3(int N) {
    int gi = blockIdx.x * 256 + threadIdx.x;
    if (gi >= N) return;
    int base = g_bsum[gi / SCAN_BLK];
    int st = g_start[gi] + base;
    g_start[gi] = st;
    g_cursor[gi] = st;
}

__global__ __launch_bounds__(256) void k_fill(const int* __restrict__ ei, int E) {
    int e = blockIdx.x * 256 + threadIdx.x;
    if (e >= E) return;
    int src = ei[e];
    int dst = ei[E + e];
    int pos = atomicAdd(&g_cursor[dst], 1);
    g_srcs[pos] = src;
}

// ---------------------------------------------------------------------------
// K_agg: (1+eps)*x[i](fp32) + sum of fp16 neighbor rows. Unroll 4 for MLP.
// ---------------------------------------------------------------------------
__global__ __launch_bounds__(256) void k_agg(const float* __restrict__ x,
                                             const float* __restrict__ epsp,
                                             float* __restrict__ agg, int N) {
    int tid = threadIdx.x;
    int i = blockIdx.x * 16 + (tid >> 4);
    int q = tid & 15;
    if (i >= N) return;
    float s = 1.0f + epsp[0];
    float4 xv = ((const float4*)x)[(size_t)i * 16 + q];
    float4 acc = make_float4(xv.x * s, xv.y * s, xv.z * s, xv.w * s);
    int j = g_start[i];
    int je = g_start[i + 1];
    for (; j + 4 <= je; j += 4) {
        int s0 = g_srcs[j], s1 = g_srcs[j+1], s2 = g_srcs[j+2], s3 = g_srcs[j+3];
        uint2 u0 = g_xh[(size_t)s0 * 16 + q];
        uint2 u1 = g_xh[(size_t)s1 * 16 + q];
        uint2 u2 = g_xh[(size_t)s2 * 16 + q];
        uint2 u3 = g_xh[(size_t)s3 * 16 + q];
        float2 a0 = __half22float2(*(__half2*)&u0.x), b0 = __half22float2(*(__half2*)&u0.y);
        float2 a1 = __half22float2(*(__half2*)&u1.x), b1 = __half22float2(*(__half2*)&u1.y);
        float2 a2 = __half22float2(*(__half2*)&u2.x), b2 = __half22float2(*(__half2*)&u2.y);
        float2 a3 = __half22float2(*(__half2*)&u3.x), b3 = __half22float2(*(__half2*)&u3.y);
        acc.x += (a0.x + a1.x) + (a2.x + a3.x);
        acc.y += (a0.y + a1.y) + (a2.y + a3.y);
        acc.z += (b0.x + b1.x) + (b2.x + b3.x);
        acc.w += (b0.y + b1.y) + (b2.y + b3.y);
    }
    for (; j < je; j++) {
        uint2 u = g_xh[(size_t)g_srcs[j] * 16 + q];
        float2 f0 = __half22float2(*(__half2*)&u.x);
        float2 f1 = __half22float2(*(__half2*)&u.y);
        acc.x += f0.x; acc.y += f0.y; acc.z += f1.x; acc.w += f1.y;
    }
    ((float4*)agg)[(size_t)i * 16 + q] = acc;
}

// ---------------------------------------------------------------------------
// 3xTF32 tensor-core GEMM + fused BN stats.
// Block = 256 thr, tile 64 rows x 64 cols. 8 warps: warp w -> m-strip (w&3),
// n-half (w>>2). mma.m16n8k8.tf32, hi/lo split for fp32-class accuracy.
// Smem stride 68 (uint2) => conflict-free STS.64 staging and LDS.64 frags.
// ---------------------------------------------------------------------------
__device__ __forceinline__ uint2 split_tf32(float v) {
    unsigned hb;
    asm("cvt.rna.tf32.f32 %0, %1;" : "=r"(hb) : "f"(v));
    float lo = v - __uint_as_float(hb);
    unsigned lb;
    asm("cvt.rna.tf32.f32 %0, %1;" : "=r"(lb) : "f"(lo));
    uint2 r; r.x = hb; r.y = lb;
    return r;
}

#define MMA_TF32(c, a0, a1, a2, a3, b0, b1)                                   \
    asm volatile(                                                             \
        "mma.sync.aligned.m16n8k8.row.col.f32.tf32.tf32.f32 "                 \
        "{%0,%1,%2,%3}, {%4,%5,%6,%7}, {%8,%9}, {%0,%1,%2,%3};"               \
        : "+f"(c[0]), "+f"(c[1]), "+f"(c[2]), "+f"(c[3])                      \
        : "r"(a0), "r"(a1), "r"(a2), "r"(a3), "r"(b0), "r"(b1))

__global__ __launch_bounds__(256) void k_gemm_mma(
    const float* __restrict__ in, const float* __restrict__ W,
    const float* __restrict__ b, float* __restrict__ out,
    float* __restrict__ statsOut,
    const float* __restrict__ statsIn,
    const float* __restrict__ gamma, const float* __restrict__ beta,
    int N, int applyBNin)
{
    extern __shared__ uint2 dyn[];
    uint2* Xs = dyn;               // [row 64][k 64] stride 68
    uint2* Wsm = dyn + 64 * 68;    // [k 64][n 64] stride 68
    __shared__ float Bs[64], SC[64], SH[64];
    __shared__ float redS[8][32], redQ[8][32];

    const int tid = threadIdx.x;
    const int row0 = blockIdx.x * 64;

    if (tid < 64) {
        Bs[tid] = b[tid];
        if (applyBNin) {
            float invN = 1.0f / (float)N;
            float mean = statsIn[tid] * invN;
            float var  = statsIn[64 + tid] * invN - mean * mean;
            float sc = gamma[tid] * rsqrtf(var + 1e-5f);
            SC[tid] = sc;
            SH[tid] = beta[tid] - mean * sc;
        }
    }
    __syncthreads();

    // Stage W [k][n] (hi,lo). Coalesced reads; consecutive-n STS (no conflict).
    #pragma unroll
    for (int it = 0; it < 16; it++) {
        int idx = tid + it * 256;
        int k = idx >> 6, n = idx & 63;
        Wsm[k * 68 + n] = split_tf32(W[idx]);
    }
    // Stage X [row][k] (hi,lo) with optional BN+ReLU.
    #pragma unroll
    for (int it = 0; it < 16; it++) {
        int idx = tid + it * 256;
        int row = idx >> 6, c = idx & 63;
        int gr = row0 + row;
        float v = (gr < N) ? in[(size_t)gr * 64 + c] : 0.f;
        if (applyBNin) v = fmaxf(fmaf(v, SC[c], SH[c]), 0.f);
        Xs[row * 68 + c] = split_tf32(v);
    }
    __syncthreads();

    const int w = tid >> 5, lane = tid & 31;
    const int ms = w & 3, nh = w >> 2;
    const int g = lane >> 2, t4 = lane & 3;
    const int mbase = ms * 16;
    const int nbase = nh * 32;

    float c_[4][4];
    #pragma unroll
    for (int nt = 0; nt < 4; nt++) {
        int col0 = nbase + nt * 8 + 2 * t4;
        c_[nt][0] = Bs[col0]; c_[nt][1] = Bs[col0 + 1];
        c_[nt][2] = Bs[col0]; c_[nt][3] = Bs[col0 + 1];
    }

    #pragma unroll
    for (int kk = 0; kk < 8; kk++) {
        int k0 = kk * 8;
        uint2 A0 = Xs[(mbase + g) * 68 + k0 + t4];
        uint2 A1 = Xs[(mbase + g + 8) * 68 + k0 + t4];
        uint2 A2 = Xs[(mbase + g) * 68 + k0 + t4 + 4];
        uint2 A3 = Xs[(mbase + g + 8) * 68 + k0 + t4 + 4];
        #pragma unroll
        for (int nt = 0; nt < 4; nt++) {
            int n = nbase + nt * 8 + g;
            uint2 B0 = Wsm[(k0 + t4) * 68 + n];
            uint2 B1 = Wsm[(k0 + t4 + 4) * 68 + n];
            MMA_TF32(c_[nt], A0.x, A1.x, A2.x, A3.x, B0.x, B1.x);  // hi*hi
            MMA_TF32(c_[nt], A0.x, A1.x, A2.x, A3.x, B0.y, B1.y);  // hi*lo
            MMA_TF32(c_[nt], A0.y, A1.y, A2.y, A3.y, B0.x, B1.x);  // lo*hi
        }
    }

    // Epilogue: store + column stats (guard rows >= N)
    int rg0 = row0 + mbase + g;
    int rg8 = rg0 + 8;
    #pragma unroll
    for (int nt = 0; nt < 4; nt++) {
        int col0 = nbase + nt * 8 + 2 * t4;
        float s0 = 0.f, s1 = 0.f, q0 = 0.f, q1 = 0.f;
        if (rg0 < N) {
            *(float2*)&out[(size_t)rg0 * 64 + col0] = make_float2(c_[nt][0], c_[nt][1]);
            s0 += c_[nt][0]; s1 += c_[nt][1];
            q0 += c_[nt][0] * c_[nt][0]; q1 += c_[nt][1] * c_[nt][1];
        }
        if (rg8 < N) {
            *(float2*)&out[(size_t)rg8 * 64 + col0] = make_float2(c_[nt][2], c_[nt][3]);
            s0 += c_[nt][2]; s1 += c_[nt][3];
            q0 += c_[nt][2] * c_[nt][2]; q1 += c_[nt][3] * c_[nt][3];
        }
        #pragma unroll
        for (int o = 16; o >= 4; o >>= 1) {
            s0 += __shfl_down_sync(0xFFFFFFFFu, s0, o);
            s1 += __shfl_down_sync(0xFFFFFFFFu, s1, o);
            q0 += __shfl_down_sync(0xFFFFFFFFu, q0, o);
            q1 += __shfl_down_sync(0xFFFFFFFFu, q1, o);
        }
        if (lane < 4) {
            redS[w][nt * 8 + 2 * t4] = s0;
            redS[w][nt * 8 + 2 * t4 + 1] = s1;
            redQ[w][nt * 8 + 2 * t4] = q0;
            redQ[w][nt * 8 + 2 * t4 + 1] = q1;
        }
    }
    __syncthreads();
    if (tid < 64) {
        int hh = tid >> 5, lc = tid & 31;
        float s = redS[hh * 4 + 0][lc] + redS[hh * 4 + 1][lc]
                + redS[hh * 4 + 2][lc] + redS[hh * 4 + 3][lc];
        float q = redQ[hh * 4 + 0][lc] + redQ[hh * 4 + 1][lc]
                + redQ[hh * 4 + 2][lc] + redQ[hh * 4 + 3][lc];
        atomicAdd(&statsOut[tid], s);
        atomicAdd(&statsOut[64 + tid], q);
    }
}

// ---------------------------------------------------------------------------
// K_final: out = x + relu(BN(t2))
// ---------------------------------------------------------------------------
__global__ __launch_bounds__(256) void k_final(const float* __restrict__ x,
                                               const float* __restrict__ t2,
                                               const float* __restrict__ statsIn,
                                               const float* __restrict__ gamma,
                                               const float* __restrict__ beta,
                                               float* __restrict__ out, int N) {
    __shared__ float SC[64];
    __shared__ float SH[64];
    int tid = threadIdx.x;
    if (tid < 64) {
        float invN = 1.0f / (float)N;
        float mean = statsIn[tid] * invN;
        float var  = statsIn[64 + tid] * invN - mean * mean;
        float sc = gamma[tid] * rsqrtf(var + 1e-5f);
        SC[tid] = sc;
        SH[tid] = beta[tid] - mean * sc;
    }
    __syncthreads();
    int n4 = N * 16;
    for (int i = blockIdx.x * 256 + tid; i < n4; i += gridDim.x * 256) {
        int c = (i & 15) * 4;
        float4 v = ((const float4*)t2)[i];
        float4 xv = ((const float4*)x)[i];
        float4 o;
        o.x = xv.x + fmaxf(fmaf(v.x, SC[c + 0], SH[c + 0]), 0.f);
        o.y = xv.y + fmaxf(fmaf(v.y, SC[c + 1], SH[c + 1]), 0.f);
        o.z = xv.z + fmaxf(fmaf(v.z, SC[c + 2], SH[c + 2]), 0.f);
        o.w = xv.w + fmaxf(fmaf(v.w, SC[c + 3], SH[c + 3]), 0.f);
        ((float4*)out)[i] = o;
    }
}

// ---------------------------------------------------------------------------
extern "C" void kernel_launch(void* const* d_in, const int* in_sizes, int n_in,
                              void* d_out, int out_size) {
    const float* x    = (const float*)d_in[0];
    const int*   ei   = (const int*)d_in[1];
    const float* eps  = (const float*)d_in[2];
    const float* W1   = (const float*)d_in[3];
    const float* b1   = (const float*)d_in[4];
    const float* g1   = (const float*)d_in[5];
    const float* beta1= (const float*)d_in[6];
    const float* W2   = (const float*)d_in[7];
    const float* b2   = (const float*)d_in[8];
    const float* gh   = (const float*)d_in[9];
    const float* betah= (const float*)d_in[10];
    float* out = (float*)d_out;

    int N = in_sizes[0] / D;
    int E = in_sizes[1] / 2;
    if (N > MAXN) N = MAXN;
    if (E > MAXE) E = MAXE;

    float* agg;   cudaGetSymbolAddress((void**)&agg, g_agg);
    float* t1;    cudaGetSymbolAddress((void**)&t1, g_t1);
    float* stats; cudaGetSymbolAddress((void**)&stats, g_stats);

    const int gemmSmem = 2 * 64 * 68 * (int)sizeof(uint2);   // 69632 B
    cudaFuncSetAttribute(k_gemm_mma, cudaFuncAttributeMaxDynamicSharedMemorySize,
                         gemmSmem);

    int eBlocks = (E + 255) / 256;
    int nScanBlocks = (N + SCAN_BLK - 1) / SCAN_BLK;

    k_prep<<<(N * 16 + 255) / 256, 256>>>(x, N, E);
    k_hist<<<eBlocks, 256>>>(ei, E);
    k_scan1<<<nScanBlocks, SCAN_BLK>>>(N);
    k_scan2<<<1, SCAN_BLK>>>(nScanBlocks);
    k_scan3<<<(N + 255) / 256, 256>>>(N);
    k_fill<<<eBlocks, 256>>>(ei, E);
    k_agg<<<(N + 15) / 16, 256>>>(x, eps, agg, N);

    int gemmBlocks = (N + 63) / 64;
    k_gemm_mma<<<gemmBlocks, 256, gemmSmem>>>(agg, W1, b1, t1, stats,
                                              nullptr, nullptr, nullptr, N, 0);
    k_gemm_mma<<<gemmBlocks, 256, gemmSmem>>>(t1, W2, b2, agg, stats + 128,
                                              stats, g1, beta1, N, 1);

    k_final<<<(N * 16 + 255) / 256, 256>>>(x, agg, stats + 128, gh, betah, out, N);
}

// round 7
// speedup vs baseline: 1.0137x; 1.0137x over previous
#include <cuda_runtime.h>
#include <cuda_fp16.h>
#include <cstdint>

#define D 64
#define MAXN 100000
#define MAXE 1600000
#define SCAN_BLK 1024

// Scratch (device globals — no allocation allowed)
__device__ float g_agg[MAXN * D];      // agg result; later reused as t2
__device__ float g_t1[MAXN * D];       // output of first Linear
__device__ float g_stats[256];         // sum1[64], sq1[64], sum2[64], sq2[64]
__device__ uint2 g_xh[MAXN * 16];      // x staged as fp16 (64 halfs/row)
__device__ int   g_cnt[MAXN + SCAN_BLK];
__device__ int   g_start[MAXN + 1];
__device__ int   g_cursor[MAXN];
__device__ int   g_srcs[MAXE];
__device__ int   g_bsum[SCAN_BLK];

// ---------------------------------------------------------------------------
// K_prep: stage x as fp16, zero stats + degree counters, set g_start[N]=E
// ---------------------------------------------------------------------------
__global__ __launch_bounds__(256) void k_prep(const float* __restrict__ x,
                                              int N, int E) {
    int i = blockIdx.x * 256 + threadIdx.x;
    if (i < 256) g_stats[i] = 0.f;
    if (i < N + SCAN_BLK) g_cnt[i] = 0;
    if (i == 0) g_start[N] = E;
    int n4 = N * 16;
    if (i >= n4) return;
    float4 v = ((const float4*)x)[i];
    __half2 h0 = __floats2half2_rn(v.x, v.y);
    __half2 h1 = __floats2half2_rn(v.z, v.w);
    uint2 u;
    u.x = *(unsigned*)&h0;
    u.y = *(unsigned*)&h1;
    g_xh[i] = u;
}

__global__ __launch_bounds__(256) void k_hist(const int* __restrict__ ei, int E) {
    int e = blockIdx.x * 256 + threadIdx.x;
    if (e >= E) return;
    atomicAdd(&g_cnt[ei[E + e]], 1);
}

__device__ __forceinline__ int block_scan_1024(int v, int* warpsum, int* total) {
    int lane = threadIdx.x & 31, wid = threadIdx.x >> 5;
    int inc = v;
    #pragma unroll
    for (int o = 1; o < 32; o <<= 1) {
        int u = __shfl_up_sync(0xFFFFFFFFu, inc, o);
        if (lane >= o) inc += u;
    }
    if (lane == 31) warpsum[wid] = inc;
    __syncthreads();
    if (wid == 0) {
        int w = warpsum[lane];
        #pragma unroll
        for (int o = 1; o < 32; o <<= 1) {
            int u = __shfl_up_sync(0xFFFFFFFFu, w, o);
            if (lane >= o) w += u;
        }
        warpsum[lane] = w;
    }
    __syncthreads();
    int base = (wid > 0) ? warpsum[wid - 1] : 0;
    *total = warpsum[31];
    return inc + base;
}

__global__ __launch_bounds__(SCAN_BLK) void k_scan1(int N) {
    __shared__ int warpsum[32];
    int gi = blockIdx.x * SCAN_BLK + threadIdx.x;
    int v = (gi < N) ? g_cnt[gi] : 0;
    int total;
    int incl = block_scan_1024(v, warpsum, &total);
    if (gi < N) {
        g_cnt[gi] = incl;
        g_start[gi] = incl - v;
    }
    if (threadIdx.x == SCAN_BLK - 1) g_bsum[blockIdx.x] = total;
}

__global__ __launch_bounds__(SCAN_BLK) void k_scan2(int nb) {
    __shared__ int warpsum[32];
    int t = threadIdx.x;
    int v = (t < nb) ? g_bsum[t] : 0;
    int total;
    int incl = block_scan_1024(v, warpsum, &total);
    if (t < nb) g_bsum[t] = incl - v;
}

__global__ __launch_bounds__(256) void k_scan3(int N) {
    int gi = blockIdx.x * 256 + threadIdx.x;
    if (gi >= N) return;
    int base = g_bsum[gi / SCAN_BLK];
    int st = g_start[gi] + base;
    g_start[gi] = st;
    g_cursor[gi] = st;
}

__global__ __launch_bounds__(256) void k_fill(const int* __restrict__ ei, int E) {
    int e = blockIdx.x * 256 + threadIdx.x;
    if (e >= E) return;
    int src = ei[e];
    int dst = ei[E + e];
    int pos = atomicAdd(&g_cursor[dst], 1);
    g_srcs[pos] = src;
}

// ---------------------------------------------------------------------------
// K_agg: (1+eps)*x[i](fp32) + sum of fp16 neighbor rows.
// 16 threads per node. Aligned int4 loads of g_srcs (one LDG.128 broadcast
// instead of 4 scalar LDG per group) + unroll-4 gathers for MLP.
// ---------------------------------------------------------------------------
__global__ __launch_bounds__(256) void k_agg(const float* __restrict__ x,
                                             const float* __restrict__ epsp,
                                             float* __restrict__ agg, int N) {
    int tid = threadIdx.x;
    int i = blockIdx.x * 16 + (tid >> 4);
    int q = tid & 15;
    if (i >= N) return;
    float s = 1.0f + epsp[0];
    float4 xv = ((const float4*)x)[(size_t)i * 16 + q];
    float4 acc = make_float4(xv.x * s, xv.y * s, xv.z * s, xv.w * s);
    int j = g_start[i];
    int je = g_start[i + 1];
    // prologue to 16B alignment of &g_srcs[j]
    for (; j < je && (j & 3); j++) {
        uint2 u = g_xh[(size_t)g_srcs[j] * 16 + q];
        float2 f0 = __half22float2(*(__half2*)&u.x);
        float2 f1 = __half22float2(*(__half2*)&u.y);
        acc.x += f0.x; acc.y += f0.y; acc.z += f1.x; acc.w += f1.y;
    }
    for (; j + 4 <= je; j += 4) {
        int4 s4 = *(const int4*)&g_srcs[j];
        uint2 u0 = g_xh[(size_t)s4.x * 16 + q];
        uint2 u1 = g_xh[(size_t)s4.y * 16 + q];
        uint2 u2 = g_xh[(size_t)s4.z * 16 + q];
        uint2 u3 = g_xh[(size_t)s4.w * 16 + q];
        float2 a0 = __half22float2(*(__half2*)&u0.x), b0 = __half22float2(*(__half2*)&u0.y);
        float2 a1 = __half22float2(*(__half2*)&u1.x), b1 = __half22float2(*(__half2*)&u1.y);
        float2 a2 = __half22float2(*(__half2*)&u2.x), b2 = __half22float2(*(__half2*)&u2.y);
        float2 a3 = __half22float2(*(__half2*)&u3.x), b3 = __half22float2(*(__half2*)&u3.y);
        acc.x += (a0.x + a1.x) + (a2.x + a3.x);
        acc.y += (a0.y + a1.y) + (a2.y + a3.y);
        acc.z += (b0.x + b1.x) + (b2.x + b3.x);
        acc.w += (b0.y + b1.y) + (b2.y + b3.y);
    }
    for (; j < je; j++) {
        uint2 u = g_xh[(size_t)g_srcs[j] * 16 + q];
        float2 f0 = __half22float2(*(__half2*)&u.x);
        float2 f1 = __half22float2(*(__half2*)&u.y);
        acc.x += f0.x; acc.y += f0.y; acc.z += f1.x; acc.w += f1.y;
    }
    ((float4*)agg)[(size_t)i * 16 + q] = acc;
}

// ---------------------------------------------------------------------------
// GEMM + BN stats (R2 FFMA version — known 30.4us)
// ---------------------------------------------------------------------------
__global__ __launch_bounds__(256) void k_gemm_bn(
    const float* __restrict__ in, const float* __restrict__ W,
    const float* __restrict__ b, float* __restrict__ out,
    float* __restrict__ statsOut,
    const float* __restrict__ statsIn,
    const float* __restrict__ gamma, const float* __restrict__ beta,
    int N, int applyBNin)
{
    __shared__ float Xs[64 * 68];
    __shared__ float Ws[64 * 64];
    __shared__ float Bs[64];
    __shared__ float SC[64];
    __shared__ float SH[64];
    __shared__ float red[16 * 64];

    const int tid = threadIdx.x;
    const int t = tid & 15;
    const int r = tid >> 4;
    const int row0 = blockIdx.x * 64;

    #pragma unroll
    for (int i = 0; i < 4; i++) {
        int lin = tid + i * 256;
        ((float4*)Ws)[lin] = ((const float4*)W)[lin];
    }
    if (tid < 64) {
        Bs[tid] = b[tid];
        if (applyBNin) {
            float invN = 1.0f / (float)N;
            float mean = statsIn[tid] * invN;
            float var  = statsIn[64 + tid] * invN - mean * mean;
            float sc = gamma[tid] * rsqrtf(var + 1e-5f);
            SC[tid] = sc;
            SH[tid] = beta[tid] - mean * sc;
        }
    }
    __syncthreads();

    #pragma unroll
    for (int i = 0; i < 4; i++) {
        int lin = tid + i * 256;
        int row = lin >> 4;
        int c4 = lin & 15;
        float4 v = make_float4(0.f, 0.f, 0.f, 0.f);
        int gr = row0 + row;
        if (gr < N) v = ((const float4*)in)[(size_t)gr * 16 + c4];
        if (applyBNin) {
            int c = c4 * 4;
            v.x = fmaxf(fmaf(v.x, SC[c + 0], SH[c + 0]), 0.f);
            v.y = fmaxf(fmaf(v.y, SC[c + 1], SH[c + 1]), 0.f);
            v.z = fmaxf(fmaf(v.z, SC[c + 2], SH[c + 2]), 0.f);
            v.w = fmaxf(fmaf(v.w, SC[c + 3], SH[c + 3]), 0.f);
        }
        *(float4*)&Xs[row * 68 + c4 * 4] = v;
    }
    __syncthreads();

    float4 a0 = make_float4(0.f,0.f,0.f,0.f);
    float4 a1 = a0, a2 = a0, a3 = a0;
    const int xb = (r * 4) * 68;
    #pragma unroll
    for (int k = 0; k < 64; k++) {
        float4 w = *(const float4*)&Ws[k * 64 + t * 4];
        float x0 = Xs[xb + k];
        float x1 = Xs[xb + 68 + k];
        float x2 = Xs[xb + 136 + k];
        float x3 = Xs[xb + 204 + k];
        a0.x = fmaf(x0, w.x, a0.x); a0.y = fmaf(x0, w.y, a0.y);
        a0.z = fmaf(x0, w.z, a0.z); a0.w = fmaf(x0, w.w, a0.w);
        a1.x = fmaf(x1, w.x, a1.x); a1.y = fmaf(x1, w.y, a1.y);
        a1.z = fmaf(x1, w.z, a1.z); a1.w = fmaf(x1, w.w, a1.w);
        a2.x = fmaf(x2, w.x, a2.x); a2.y = fmaf(x2, w.y, a2.y);
        a2.z = fmaf(x2, w.z, a2.z); a2.w = fmaf(x2, w.w, a2.w);
        a3.x = fmaf(x3, w.x, a3.x); a3.y = fmaf(x3, w.y, a3.y);
        a3.z = fmaf(x3, w.z, a3.z); a3.w = fmaf(x3, w.w, a3.w);
    }
    float4 bb = *(const float4*)&Bs[t * 4];
    a0.x += bb.x; a0.y += bb.y; a0.z += bb.z; a0.w += bb.w;
    a1.x += bb.x; a1.y += bb.y; a1.z += bb.z; a1.w += bb.w;
    a2.x += bb.x; a2.y += bb.y; a2.z += bb.z; a2.w += bb.w;
    a3.x += bb.x; a3.y += bb.y; a3.z += bb.z; a3.w += bb.w;

    float4 ls = make_float4(0.f,0.f,0.f,0.f);
    float4 lq = ls;
    float4 acc[4] = {a0, a1, a2, a3};
    #pragma unroll
    for (int j = 0; j < 4; j++) {
        int row = row0 + r * 4 + j;
        if (row < N) {
            *(float4*)&out[(size_t)row * 64 + t * 4] = acc[j];
            ls.x += acc[j].x; ls.y += acc[j].y; ls.z += acc[j].z; ls.w += acc[j].w;
            lq.x += acc[j].x * acc[j].x; lq.y += acc[j].y * acc[j].y;
            lq.z += acc[j].z * acc[j].z; lq.w += acc[j].w * acc[j].w;
        }
    }

    __syncthreads();
    *(float4*)&red[r * 64 + t * 4] = ls;
    __syncthreads();
    if (tid < 64) {
        float s = 0.f;
        #pragma unroll
        for (int rr = 0; rr < 16; rr++) s += red[rr * 64 + tid];
        atomicAdd(&statsOut[tid], s);
    }
    __syncthreads();
    *(float4*)&red[r * 64 + t * 4] = lq;
    __syncthreads();
    if (tid < 64) {
        float s = 0.f;
        #pragma unroll
        for (int rr = 0; rr < 16; rr++) s += red[rr * 64 + tid];
        atomicAdd(&statsOut[64 + tid], s);
    }
}

// ---------------------------------------------------------------------------
// K_final: out = x + relu(BN(t2))
// ---------------------------------------------------------------------------
__global__ __launch_bounds__(256) void k_final(const float* __restrict__ x,
                                               const float* __restrict__ t2,
                                               const float* __restrict__ statsIn,
                                               const float* __restrict__ gamma,
                                               const float* __restrict__ beta,
                                               float* __restrict__ out, int N) {
    __shared__ float SC[64];
    __shared__ float SH[64];
    int tid = threadIdx.x;
    if (tid < 64) {
        float invN = 1.0f / (float)N;
        float mean = statsIn[tid] * invN;
        float var  = statsIn[64 + tid] * invN - mean * mean;
        float sc = gamma[tid] * rsqrtf(var + 1e-5f);
        SC[tid] = sc;
        SH[tid] = beta[tid] - mean * sc;
    }
    __syncthreads();
    int n4 = N * 16;
    for (int i = blockIdx.x * 256 + tid; i < n4; i += gridDim.x * 256) {
        int c = (i & 15) * 4;
        float4 v = ((const float4*)t2)[i];
        float4 xv = ((const float4*)x)[i];
        float4 o;
        o.x = xv.x + fmaxf(fmaf(v.x, SC[c + 0], SH[c + 0]), 0.f);
        o.y = xv.y + fmaxf(fmaf(v.y, SC[c + 1], SH[c + 1]), 0.f);
        o.z = xv.z + fmaxf(fmaf(v.z, SC[c + 2], SH[c + 2]), 0.f);
        o.w = xv.w + fmaxf(fmaf(v.w, SC[c + 3], SH[c + 3]), 0.f);
        ((float4*)out)[i] = o;
    }
}

// ---------------------------------------------------------------------------
extern "C" void kernel_launch(void* const* d_in, const int* in_sizes, int n_in,
                              void* d_out, int out_size) {
    const float* x    = (const float*)d_in[0];
    const int*   ei   = (const int*)d_in[1];
    const float* eps  = (const float*)d_in[2];
    const float* W1   = (const float*)d_in[3];
    const float* b1   = (const float*)d_in[4];
    const float* g1   = (const float*)d_in[5];
    const float* beta1= (const float*)d_in[6];
    const float* W2   = (const float*)d_in[7];
    const float* b2   = (const float*)d_in[8];
    const float* gh   = (const float*)d_in[9];
    const float* betah= (const float*)d_in[10];
    float* out = (float*)d_out;

    int N = in_sizes[0] / D;
    int E = in_sizes[1] / 2;
    if (N > MAXN) N = MAXN;
    if (E > MAXE) E = MAXE;

    float* agg;   cudaGetSymbolAddress((void**)&agg, g_agg);
    float* t1;    cudaGetSymbolAddress((void**)&t1, g_t1);
    float* stats; cudaGetSymbolAddress((void**)&stats, g_stats);

    int eBlocks = (E + 255) / 256;
    int nScanBlocks = (N + SCAN_BLK - 1) / SCAN_BLK;

    k_prep<<<(N * 16 + 255) / 256, 256>>>(x, N, E);
    k_hist<<<eBlocks, 256>>>(ei, E);
    k_scan1<<<nScanBlocks, SCAN_BLK>>>(N);
    k_scan2<<<1, SCAN_BLK>>>(nScanBlocks);
    k_scan3<<<(N + 255) / 256, 256>>>(N);
    k_fill<<<eBlocks, 256>>>(ei, E);
    k_agg<<<(N + 15) / 16, 256>>>(x, eps, agg, N);

    int gemmBlocks = (N + 63) / 64;
    k_gemm_bn<<<gemmBlocks, 256>>>(agg, W1, b1, t1, stats, nullptr, nullptr, nullptr, N, 0);
    k_gemm_bn<<<gemmBlocks, 256>>>(t1, W2, b2, agg, stats + 128, stats, g1, beta1, N, 1);

    k_final<<<(N * 16 + 255) / 256, 256>>>(x, agg, stats + 128, gh, betah, out, N);
}

// round 8
// speedup vs baseline: 1.2365x; 1.2198x over previous
#include <cuda_runtime.h>
#include <cuda_fp16.h>
#include <cstdint>

#define D 64
#define MAXN 100000
#define MAXE 1600000
#define SCAN_BLK 1024

// Scratch (device globals — no allocation allowed)
__device__ float g_agg[MAXN * D];      // agg result; later reused as t2
__device__ float g_t1[MAXN * D];       // output of first Linear
__device__ float g_stats[256];         // sum1[64], sq1[64], sum2[64], sq2[64]
__device__ uint2 g_xh[MAXN * 16];      // x staged as fp16 (64 halfs/row = 128B)
__device__ int   g_cnt[MAXN + SCAN_BLK];
__device__ int   g_start[MAXN + 1];
__device__ int   g_cursor[MAXN];
__device__ int   g_srcs[MAXE];
__device__ int   g_bsum[SCAN_BLK];

// ---------------------------------------------------------------------------
// K_prep: stage x as fp16, zero stats + degree counters, set g_start[N]=E
// ---------------------------------------------------------------------------
__global__ __launch_bounds__(256) void k_prep(const float* __restrict__ x,
                                              int N, int E) {
    int i = blockIdx.x * 256 + threadIdx.x;
    if (i < 256) g_stats[i] = 0.f;
    if (i < N + SCAN_BLK) g_cnt[i] = 0;
    if (i == 0) g_start[N] = E;
    int n4 = N * 16;
    if (i >= n4) return;
    float4 v = ((const float4*)x)[i];
    __half2 h0 = __floats2half2_rn(v.x, v.y);
    __half2 h1 = __floats2half2_rn(v.z, v.w);
    uint2 u;
    u.x = *(unsigned*)&h0;
    u.y = *(unsigned*)&h1;
    g_xh[i] = u;
}

__global__ __launch_bounds__(256) void k_hist(const int* __restrict__ ei, int E) {
    int e = blockIdx.x * 256 + threadIdx.x;
    if (e >= E) return;
    atomicAdd(&g_cnt[ei[E + e]], 1);
}

__device__ __forceinline__ int block_scan_1024(int v, int* warpsum, int* total) {
    int lane = threadIdx.x & 31, wid = threadIdx.x >> 5;
    int inc = v;
    #pragma unroll
    for (int o = 1; o < 32; o <<= 1) {
        int u = __shfl_up_sync(0xFFFFFFFFu, inc, o);
        if (lane >= o) inc += u;
    }
    if (lane == 31) warpsum[wid] = inc;
    __syncthreads();
    if (wid == 0) {
        int w = warpsum[lane];
        #pragma unroll
        for (int o = 1; o < 32; o <<= 1) {
            int u = __shfl_up_sync(0xFFFFFFFFu, w, o);
            if (lane >= o) w += u;
        }
        warpsum[lane] = w;
    }
    __syncthreads();
    int base = (wid > 0) ? warpsum[wid - 1] : 0;
    *total = warpsum[31];
    return inc + base;
}

__global__ __launch_bounds__(SCAN_BLK) void k_scan1(int N) {
    __shared__ int warpsum[32];
    int gi = blockIdx.x * SCAN_BLK + threadIdx.x;
    int v = (gi < N) ? g_cnt[gi] : 0;
    int total;
    int incl = block_scan_1024(v, warpsum, &total);
    if (gi < N) {
        g_cnt[gi] = incl;
        g_start[gi] = incl - v;
    }
    if (threadIdx.x == SCAN_BLK - 1) g_bsum[blockIdx.x] = total;
}

__global__ __launch_bounds__(SCAN_BLK) void k_scan2(int nb) {
    __shared__ int warpsum[32];
    int t = threadIdx.x;
    int v = (t < nb) ? g_bsum[t] : 0;
    int total;
    int incl = block_scan_1024(v, warpsum, &total);
    if (t < nb) g_bsum[t] = incl - v;
}

__global__ __launch_bounds__(256) void k_scan3(int N) {
    int gi = blockIdx.x * 256 + threadIdx.x;
    if (gi >= N) return;
    int base = g_bsum[gi / SCAN_BLK];
    int st = g_start[gi] + base;
    g_start[gi] = st;
    g_cursor[gi] = st;
}

__global__ __launch_bounds__(256) void k_fill(const int* __restrict__ ei, int E) {
    int e = blockIdx.x * 256 + threadIdx.x;
    if (e >= E) return;
    int src = ei[e];
    int dst = ei[E + e];
    int pos = atomicAdd(&g_cursor[dst], 1);
    g_srcs[pos] = src;
}

// ---------------------------------------------------------------------------
// K_agg: (1+eps)*x[i](fp32) + sum of fp16 neighbor rows.
// 8 threads per node, uint4 (16B) gathers: 8 LDG.128 per edge (was 16 LDG.64).
// ---------------------------------------------------------------------------
__global__ __launch_bounds__(256) void k_agg(const float* __restrict__ x,
                                             const float* __restrict__ epsp,
                                             float* __restrict__ agg, int N) {
    int tid = threadIdx.x;
    int i = blockIdx.x * 32 + (tid >> 3);
    int q = tid & 7;
    if (i >= N) return;
    float s = 1.0f + epsp[0];
    float4 x0 = ((const float4*)x)[(size_t)i * 16 + q * 2];
    float4 x1 = ((const float4*)x)[(size_t)i * 16 + q * 2 + 1];
    float4 acc0 = make_float4(x0.x * s, x0.y * s, x0.z * s, x0.w * s);
    float4 acc1 = make_float4(x1.x * s, x1.y * s, x1.z * s, x1.w * s);
    int j = g_start[i];
    int je = g_start[i + 1];
    const uint4* xh4 = (const uint4*)g_xh;
    for (; j < je; j++) {
        int src = g_srcs[j];
        uint4 u = xh4[(size_t)src * 8 + q];
        float2 f0 = __half22float2(*(__half2*)&u.x);
        float2 f1 = __half22float2(*(__half2*)&u.y);
        float2 f2 = __half22float2(*(__half2*)&u.z);
        float2 f3 = __half22float2(*(__half2*)&u.w);
        acc0.x += f0.x; acc0.y += f0.y; acc0.z += f1.x; acc0.w += f1.y;
        acc1.x += f2.x; acc1.y += f2.y; acc1.z += f3.x; acc1.w += f3.y;
    }
    ((float4*)agg)[(size_t)i * 16 + q * 2] = acc0;
    ((float4*)agg)[(size_t)i * 16 + q * 2 + 1] = acc1;
}

// ---------------------------------------------------------------------------
// fp16 HMMA GEMM (m16n8k16, fp32 accum) + fused BN stats.
// Block 256, tile 64x64. Warp w: m-strip (w&3), n-half (w>>2) — layout and
// epilogue identical to the verified TF32 kernel.
// Xs: half2 words, row stride 68 words  -> A-fragment LDS conflict-free.
// Wsm: half2 (k-pair, n), k2 stride 72  -> B-fragment LDS conflict-free.
// ---------------------------------------------------------------------------
#define MMA_F16(c, a0, a1, a2, a3, b0, b1)                                    \
    asm volatile(                                                             \
        "mma.sync.aligned.m16n8k16.row.col.f32.f16.f16.f32 "                  \
        "{%0,%1,%2,%3}, {%4,%5,%6,%7}, {%8,%9}, {%0,%1,%2,%3};"               \
        : "+f"(c[0]), "+f"(c[1]), "+f"(c[2]), "+f"(c[3])                      \
        : "r"(a0), "r"(a1), "r"(a2), "r"(a3), "r"(b0), "r"(b1))

__global__ __launch_bounds__(256) void k_gemm_hmma(
    const float* __restrict__ in, const float* __restrict__ W,
    const float* __restrict__ b, float* __restrict__ out,
    float* __restrict__ statsOut,
    const float* __restrict__ statsIn,
    const float* __restrict__ gamma, const float* __restrict__ beta,
    int N, int applyBNin)
{
    __shared__ unsigned Xs[64 * 68];    // [row][k2] half2 words, stride 68
    __shared__ unsigned Wsm[32 * 72];   // [k2][n] half2 (k-pair), stride 72
    __shared__ float Bs[64], SC[64], SH[64];
    __shared__ float redS[8][32], redQ[8][32];

    const int tid = threadIdx.x;
    const int row0 = blockIdx.x * 64;

    if (tid < 64) {
        Bs[tid] = b[tid];
        if (applyBNin) {
            float invN = 1.0f / (float)N;
            float mean = statsIn[tid] * invN;
            float var  = statsIn[64 + tid] * invN - mean * mean;
            float sc = gamma[tid] * rsqrtf(var + 1e-5f);
            SC[tid] = sc;
            SH[tid] = beta[tid] - mean * sc;
        }
    }
    __syncthreads();

    // Stage W: Wsm[k2][n] = half2(W[2k2][n], W[2k2+1][n])
    #pragma unroll
    for (int it = 0; it < 8; it++) {
        int idx = tid + it * 256;          // 0..2047
        int k2 = idx >> 6, n = idx & 63;
        float w0 = W[(2 * k2) * 64 + n];
        float w1 = W[(2 * k2 + 1) * 64 + n];
        __half2 h = __floats2half2_rn(w0, w1);
        Wsm[k2 * 72 + n] = *(unsigned*)&h;
    }
    // Stage X: Xs[row][k2] = half2(in[row][2k2], in[row][2k2+1]) after BN/ReLU
    #pragma unroll
    for (int it = 0; it < 8; it++) {
        int idx = tid + it * 256;
        int row = idx >> 5, k2 = idx & 31;
        int gr = row0 + row;
        float2 v = make_float2(0.f, 0.f);
        if (gr < N) v = ((const float2*)in)[(size_t)gr * 32 + k2];
        if (applyBNin) {
            int c = k2 * 2;
            v.x = fmaxf(fmaf(v.x, SC[c], SH[c]), 0.f);
            v.y = fmaxf(fmaf(v.y, SC[c + 1], SH[c + 1]), 0.f);
        }
        __half2 h = __floats2half2_rn(v.x, v.y);
        Xs[row * 68 + k2] = *(unsigned*)&h;
    }
    __syncthreads();

    const int w = tid >> 5, lane = tid & 31;
    const int ms = w & 3, nh = w >> 2;
    const int g = lane >> 2, t4 = lane & 3;
    const int mbase = ms * 16;
    const int nbase = nh * 32;

    float c_[4][4];
    #pragma unroll
    for (int nt = 0; nt < 4; nt++) {
        int col0 = nbase + nt * 8 + 2 * t4;
        c_[nt][0] = Bs[col0]; c_[nt][1] = Bs[col0 + 1];
        c_[nt][2] = Bs[col0]; c_[nt][3] = Bs[col0 + 1];
    }

    #pragma unroll
    for (int kk = 0; kk < 4; kk++) {        // 16 k (= 8 half2) per step
        int kb = kk * 8;
        unsigned A0 = Xs[(mbase + g) * 68 + kb + t4];
        unsigned A1 = Xs[(mbase + g + 8) * 68 + kb + t4];
        unsigned A2 = Xs[(mbase + g) * 68 + kb + t4 + 4];
        unsigned A3 = Xs[(mbase + g + 8) * 68 + kb + t4 + 4];
        #pragma unroll
        for (int nt = 0; nt < 4; nt++) {
            int n = nbase + nt * 8 + g;
            unsigned B0 = Wsm[(kb + t4) * 72 + n];
            unsigned B1 = Wsm[(kb + t4 + 4) * 72 + n];
            MMA_F16(c_[nt], A0, A1, A2, A3, B0, B1);
        }
    }

    // Epilogue: store + column stats (verified in R6)
    int rg0 = row0 + mbase + g;
    int rg8 = rg0 + 8;
    #pragma unroll
    for (int nt = 0; nt < 4; nt++) {
        int col0 = nbase + nt * 8 + 2 * t4;
        float s0 = 0.f, s1 = 0.f, q0 = 0.f, q1 = 0.f;
        if (rg0 < N) {
            *(float2*)&out[(size_t)rg0 * 64 + col0] = make_float2(c_[nt][0], c_[nt][1]);
            s0 += c_[nt][0]; s1 += c_[nt][1];
            q0 += c_[nt][0] * c_[nt][0]; q1 += c_[nt][1] * c_[nt][1];
        }
        if (rg8 < N) {
            *(float2*)&out[(size_t)rg8 * 64 + col0] = make_float2(c_[nt][2], c_[nt][3]);
            s0 += c_[nt][2]; s1 += c_[nt][3];
            q0 += c_[nt][2] * c_[nt][2]; q1 += c_[nt][3] * c_[nt][3];
        }
        #pragma unroll
        for (int o = 16; o >= 4; o >>= 1) {
            s0 += __shfl_down_sync(0xFFFFFFFFu, s0, o);
            s1 += __shfl_down_sync(0xFFFFFFFFu, s1, o);
            q0 += __shfl_down_sync(0xFFFFFFFFu, q0, o);
            q1 += __shfl_down_sync(0xFFFFFFFFu, q1, o);
        }
        if (lane < 4) {
            redS[w][nt * 8 + 2 * t4] = s0;
            redS[w][nt * 8 + 2 * t4 + 1] = s1;
            redQ[w][nt * 8 + 2 * t4] = q0;
            redQ[w][nt * 8 + 2 * t4 + 1] = q1;
        }
    }
    __syncthreads();
    if (tid < 64) {
        int hh = tid >> 5, lc = tid & 31;
        float s = redS[hh * 4 + 0][lc] + redS[hh * 4 + 1][lc]
                + redS[hh * 4 + 2][lc] + redS[hh * 4 + 3][lc];
        float q = redQ[hh * 4 + 0][lc] + redQ[hh * 4 + 1][lc]
                + redQ[hh * 4 + 2][lc] + redQ[hh * 4 + 3][lc];
        atomicAdd(&statsOut[tid], s);
        atomicAdd(&statsOut[64 + tid], q);
    }
}

// ---------------------------------------------------------------------------
// K_final: out = x + relu(BN(t2))
// ---------------------------------------------------------------------------
__global__ __launch_bounds__(256) void k_final(const float* __restrict__ x,
                                               const float* __restrict__ t2,
                                               const float* __restrict__ statsIn,
                                               const float* __restrict__ gamma,
                                               const float* __restrict__ beta,
                                               float* __restrict__ out, int N) {
    __shared__ float SC[64];
    __shared__ float SH[64];
    int tid = threadIdx.x;
    if (tid < 64) {
        float invN = 1.0f / (float)N;
        float mean = statsIn[tid] * invN;
        float var  = statsIn[64 + tid] * invN - mean * mean;
        float sc = gamma[tid] * rsqrtf(var + 1e-5f);
        SC[tid] = sc;
        SH[tid] = beta[tid] - mean * sc;
    }
    __syncthreads();
    int n4 = N * 16;
    for (int i = blockIdx.x * 256 + tid; i < n4; i += gridDim.x * 256) {
        int c = (i & 15) * 4;
        float4 v = ((const float4*)t2)[i];
        float4 xv = ((const float4*)x)[i];
        float4 o;
        o.x = xv.x + fmaxf(fmaf(v.x, SC[c + 0], SH[c + 0]), 0.f);
        o.y = xv.y + fmaxf(fmaf(v.y, SC[c + 1], SH[c + 1]), 0.f);
        o.z = xv.z + fmaxf(fmaf(v.z, SC[c + 2], SH[c + 2]), 0.f);
        o.w = xv.w + fmaxf(fmaf(v.w, SC[c + 3], SH[c + 3]), 0.f);
        ((float4*)out)[i] = o;
    }
}

// ---------------------------------------------------------------------------
extern "C" void kernel_launch(void* const* d_in, const int* in_sizes, int n_in,
                              void* d_out, int out_size) {
    const float* x    = (const float*)d_in[0];
    const int*   ei   = (const int*)d_in[1];
    const float* eps  = (const float*)d_in[2];
    const float* W1   = (const float*)d_in[3];
    const float* b1   = (const float*)d_in[4];
    const float* g1   = (const float*)d_in[5];
    const float* beta1= (const float*)d_in[6];
    const float* W2   = (const float*)d_in[7];
    const float* b2   = (const float*)d_in[8];
    const float* gh   = (const float*)d_in[9];
    const float* betah= (const float*)d_in[10];
    float* out = (float*)d_out;

    int N = in_sizes[0] / D;
    int E = in_sizes[1] / 2;
    if (N > MAXN) N = MAXN;
    if (E > MAXE) E = MAXE;

    float* agg;   cudaGetSymbolAddress((void**)&agg, g_agg);
    float* t1;    cudaGetSymbolAddress((void**)&t1, g_t1);
    float* stats; cudaGetSymbolAddress((void**)&stats, g_stats);

    int eBlocks = (E + 255) / 256;
    int nScanBlocks = (N + SCAN_BLK - 1) / SCAN_BLK;

    k_prep<<<(N * 16 + 255) / 256, 256>>>(x, N, E);
    k_hist<<<eBlocks, 256>>>(ei, E);
    k_scan1<<<nScanBlocks, SCAN_BLK>>>(N);
    k_scan2<<<1, SCAN_BLK>>>(nScanBlocks);
    k_scan3<<<(N + 255) / 256, 256>>>(N);
    k_fill<<<eBlocks, 256>>>(ei, E);
    k_agg<<<(N + 31) / 32, 256>>>(x, eps, agg, N);

    int gemmBlocks = (N + 63) / 64;
    k_gemm_hmma<<<gemmBlocks, 256>>>(agg, W1, b1, t1, stats,
                                     nullptr, nullptr, nullptr, N, 0);
    k_gemm_hmma<<<gemmBlocks, 256>>>(t1, W2, b2, agg, stats + 128,
                                     stats, g1, beta1, N, 1);

    k_final<<<(N * 16 + 255) / 256, 256>>>(x, agg, stats + 128, gh, betah, out, N);
}

// round 9
// speedup vs baseline: 1.2499x; 1.0108x over previous
#include <cuda_runtime.h>
#include <cuda_fp16.h>
#include <cstdint>

#define D 64
#define MAXN 100000
#define MAXE 1600000
#define SCAN_BLK 1024

// Scratch (device globals — no allocation allowed; zero-initialized at load,
// and every kernel sequence restores the zero-invariants it consumes)
__device__ float g_agg[MAXN * D];      // agg result; later reused as t2
__device__ float g_t1[MAXN * D];       // output of first Linear
__device__ float g_stats[256];         // sum1[64], sq1[64], sum2[64], sq2[64]
__device__ uint2 g_xh[MAXN * 16];      // x staged as fp16 (64 halfs/row = 128B)
__device__ int   g_cnt[MAXN + SCAN_BLK];  // degree hist (zeroed by k_scan after use)
__device__ int   g_start[MAXN + 1];
__device__ int   g_cursor[MAXN];
__device__ int   g_srcs[MAXE];
__device__ int   g_bsum[SCAN_BLK];
__device__ int   g_ctr;                // grid-barrier counters (self-resetting)
__device__ int   g_ctr2;

// ---------------------------------------------------------------------------
// K_prep: stage x as fp16 + degree histogram + zero stats. g_cnt is already
// zero on entry (BSS init on first call; k_scan re-zeros it for later calls).
// ---------------------------------------------------------------------------
__global__ __launch_bounds__(256) void k_prep(const float* __restrict__ x,
                                              const int* __restrict__ ei,
                                              int N, int E) {
    int i = blockIdx.x * 256 + threadIdx.x;
    if (i < 256) g_stats[i] = 0.f;
    if (i == 0) g_start[N] = E;
    if (i < E) atomicAdd(&g_cnt[ei[E + i]], 1);
    int n4 = N * 16;
    if (i >= n4) return;
    float4 v = ((const float4*)x)[i];
    __half2 h0 = __floats2half2_rn(v.x, v.y);
    __half2 h1 = __floats2half2_rn(v.z, v.w);
    uint2 u;
    u.x = *(unsigned*)&h0;
    u.y = *(unsigned*)&h1;
    g_xh[i] = u;
}

__device__ __forceinline__ int block_scan_1024(int v, int* warpsum, int* total) {
    int lane = threadIdx.x & 31, wid = threadIdx.x >> 5;
    int inc = v;
    #pragma unroll
    for (int o = 1; o < 32; o <<= 1) {
        int u = __shfl_up_sync(0xFFFFFFFFu, inc, o);
        if (lane >= o) inc += u;
    }
    if (lane == 31) warpsum[wid] = inc;
    __syncthreads();
    if (wid == 0) {
        int w = warpsum[lane];
        #pragma unroll
        for (int o = 1; o < 32; o <<= 1) {
            int u = __shfl_up_sync(0xFFFFFFFFu, w, o);
            if (lane >= o) w += u;
        }
        warpsum[lane] = w;
    }
    __syncthreads();
    int base = (wid > 0) ? warpsum[wid - 1] : 0;
    *total = warpsum[31];
    return inc + base;
}

// ---------------------------------------------------------------------------
// K_scan: single-kernel exclusive scan of degrees -> g_start/g_cursor.
// Grid (98 blocks) <= 148 SMs => fully resident => software barrier is safe.
// Re-zeros g_cnt (restores k_prep's invariant) and self-resets counters.
// ---------------------------------------------------------------------------
__global__ __launch_bounds__(SCAN_BLK) void k_scan(int N) {
    __shared__ int warpsum[32];
    __shared__ int s_base;
    int gi = blockIdx.x * SCAN_BLK + threadIdx.x;
    int v = (gi < N) ? g_cnt[gi] : 0;
    if (gi < N) g_cnt[gi] = 0;                 // restore zero-invariant
    int total;
    int incl = block_scan_1024(v, warpsum, &total);

    if (threadIdx.x == 0) {
        g_bsum[blockIdx.x] = total;
        __threadfence();
        atomicAdd(&g_ctr, 1);
        while (atomicAdd(&g_ctr, 0) < (int)gridDim.x) {}
        __threadfence();
    }
    __syncthreads();

    // base = sum of predecessor block totals (warp 0)
    if (threadIdx.x < 32) {
        int base = 0;
        for (int j = threadIdx.x; j < (int)blockIdx.x; j += 32) base += g_bsum[j];
        #pragma unroll
        for (int o = 16; o >= 1; o >>= 1) base += __shfl_down_sync(0xFFFFFFFFu, base, o);
        if (threadIdx.x == 0) s_base = base;
    }
    __syncthreads();

    if (gi < N) {
        int st = s_base + incl - v;            // exclusive + global base
        g_start[gi] = st;
        g_cursor[gi] = st;
    }

    // self-reset counters once every block is past the spin
    if (threadIdx.x == 0) {
        int done = atomicAdd(&g_ctr2, 1);
        if (done == (int)gridDim.x - 1) { g_ctr = 0; g_ctr2 = 0; }
    }
}

__global__ __launch_bounds__(256) void k_fill(const int* __restrict__ ei, int E) {
    int e = blockIdx.x * 256 + threadIdx.x;
    if (e >= E) return;
    int src = ei[e];
    int dst = ei[E + e];
    int pos = atomicAdd(&g_cursor[dst], 1);
    g_srcs[pos] = src;
}

// ---------------------------------------------------------------------------
// K_agg: (1+eps)*x[i](fp32) + sum of fp16 neighbor rows.
// 8 threads per node, uint4 (16B) gathers. (R8 version — best so far.)
// ---------------------------------------------------------------------------
__global__ __launch_bounds__(256) void k_agg(const float* __restrict__ x,
                                             const float* __restrict__ epsp,
                                             float* __restrict__ agg, int N) {
    int tid = threadIdx.x;
    int i = blockIdx.x * 32 + (tid >> 3);
    int q = tid & 7;
    if (i >= N) return;
    float s = 1.0f + epsp[0];
    float4 x0 = ((const float4*)x)[(size_t)i * 16 + q * 2];
    float4 x1 = ((const float4*)x)[(size_t)i * 16 + q * 2 + 1];
    float4 acc0 = make_float4(x0.x * s, x0.y * s, x0.z * s, x0.w * s);
    float4 acc1 = make_float4(x1.x * s, x1.y * s, x1.z * s, x1.w * s);
    int j = g_start[i];
    int je = g_start[i + 1];
    const uint4* xh4 = (const uint4*)g_xh;
    for (; j < je; j++) {
        int src = g_srcs[j];
        uint4 u = xh4[(size_t)src * 8 + q];
        float2 f0 = __half22float2(*(__half2*)&u.x);
        float2 f1 = __half22float2(*(__half2*)&u.y);
        float2 f2 = __half22float2(*(__half2*)&u.z);
        float2 f3 = __half22float2(*(__half2*)&u.w);
        acc0.x += f0.x; acc0.y += f0.y; acc0.z += f1.x; acc0.w += f1.y;
        acc1.x += f2.x; acc1.y += f2.y; acc1.z += f3.x; acc1.w += f3.y;
    }
    ((float4*)agg)[(size_t)i * 16 + q * 2] = acc0;
    ((float4*)agg)[(size_t)i * 16 + q * 2 + 1] = acc1;
}

// ---------------------------------------------------------------------------
// fp16 HMMA GEMM (m16n8k16, fp32 accum) + fused BN stats. (R8 — verified)
// ---------------------------------------------------------------------------
#define MMA_F16(c, a0, a1, a2, a3, b0, b1)                                    \
    asm volatile(                                                             \
        "mma.sync.aligned.m16n8k16.row.col.f32.f16.f16.f32 "                  \
        "{%0,%1,%2,%3}, {%4,%5,%6,%7}, {%8,%9}, {%0,%1,%2,%3};"               \
        : "+f"(c[0]), "+f"(c[1]), "+f"(c[2]), "+f"(c[3])                      \
        : "r"(a0), "r"(a1), "r"(a2), "r"(a3), "r"(b0), "r"(b1))

__global__ __launch_bounds__(256) void k_gemm_hmma(
    const float* __restrict__ in, const float* __restrict__ W,
    const float* __restrict__ b, float* __restrict__ out,
    float* __restrict__ statsOut,
    const float* __restrict__ statsIn,
    const float* __restrict__ gamma, const float* __restrict__ beta,
    int N, int applyBNin)
{
    __shared__ unsigned Xs[64 * 68];
    __shared__ unsigned Wsm[32 * 72];
    __shared__ float Bs[64], SC[64], SH[64];
    __shared__ float redS[8][32], redQ[8][32];

    const int tid = threadIdx.x;
    const int row0 = blockIdx.x * 64;

    if (tid < 64) {
        Bs[tid] = b[tid];
        if (applyBNin) {
            float invN = 1.0f / (float)N;
            float mean = statsIn[tid] * invN;
            float var  = statsIn[64 + tid] * invN - mean * mean;
            float sc = gamma[tid] * rsqrtf(var + 1e-5f);
            SC[tid] = sc;
            SH[tid] = beta[tid] - mean * sc;
        }
    }
    __syncthreads();

    #pragma unroll
    for (int it = 0; it < 8; it++) {
        int idx = tid + it * 256;
        int k2 = idx >> 6, n = idx & 63;
        float w0 = W[(2 * k2) * 64 + n];
        float w1 = W[(2 * k2 + 1) * 64 + n];
        __half2 h = __floats2half2_rn(w0, w1);
        Wsm[k2 * 72 + n] = *(unsigned*)&h;
    }
    #pragma unroll
    for (int it = 0; it < 8; it++) {
        int idx = tid + it * 256;
        int row = idx >> 5, k2 = idx & 31;
        int gr = row0 + row;
        float2 v = make_float2(0.f, 0.f);
        if (gr < N) v = ((const float2*)in)[(size_t)gr * 32 + k2];
        if (applyBNin) {
            int c = k2 * 2;
            v.x = fmaxf(fmaf(v.x, SC[c], SH[c]), 0.f);
            v.y = fmaxf(fmaf(v.y, SC[c + 1], SH[c + 1]), 0.f);
        }
        __half2 h = __floats2half2_rn(v.x, v.y);
        Xs[row * 68 + k2] = *(unsigned*)&h;
    }
    __syncthreads();

    const int w = tid >> 5, lane = tid & 31;
    const int ms = w & 3, nh = w >> 2;
    const int g = lane >> 2, t4 = lane & 3;
    const int mbase = ms * 16;
    const int nbase = nh * 32;

    float c_[4][4];
    #pragma unroll
    for (int nt = 0; nt < 4; nt++) {
        int col0 = nbase + nt * 8 + 2 * t4;
        c_[nt][0] = Bs[col0]; c_[nt][1] = Bs[col0 + 1];
        c_[nt][2] = Bs[col0]; c_[nt][3] = Bs[col0 + 1];
    }

    #pragma unroll
    for (int kk = 0; kk < 4; kk++) {
        int kb = kk * 8;
        unsigned A0 = Xs[(mbase + g) * 68 + kb + t4];
        unsigned A1 = Xs[(mbase + g + 8) * 68 + kb + t4];
        unsigned A2 = Xs[(mbase + g) * 68 + kb + t4 + 4];
        unsigned A3 = Xs[(mbase + g + 8) * 68 + kb + t4 + 4];
        #pragma unroll
        for (int nt = 0; nt < 4; nt++) {
            int n = nbase + nt * 8 + g;
            unsigned B0 = Wsm[(kb + t4) * 72 + n];
            unsigned B1 = Wsm[(kb + t4 + 4) * 72 + n];
            MMA_F16(c_[nt], A0, A1, A2, A3, B0, B1);
        }
    }

    int rg0 = row0 + mbase + g;
    int rg8 = rg0 + 8;
    #pragma unroll
    for (int nt = 0; nt < 4; nt++) {
        int col0 = nbase + nt * 8 + 2 * t4;
        float s0 = 0.f, s1 = 0.f, q0 = 0.f, q1 = 0.f;
        if (rg0 < N) {
            *(float2*)&out[(size_t)rg0 * 64 + col0] = make_float2(c_[nt][0], c_[nt][1]);
            s0 += c_[nt][0]; s1 += c_[nt][1];
            q0 += c_[nt][0] * c_[nt][0]; q1 += c_[nt][1] * c_[nt][1];
        }
        if (rg8 < N) {
            *(float2*)&out[(size_t)rg8 * 64 + col0] = make_float2(c_[nt][2], c_[nt][3]);
            s0 += c_[nt][2]; s1 += c_[nt][3];
            q0 += c_[nt][2] * c_[nt][2]; q1 += c_[nt][3] * c_[nt][3];
        }
        #pragma unroll
        for (int o = 16; o >= 4; o >>= 1) {
            s0 += __shfl_down_sync(0xFFFFFFFFu, s0, o);
            s1 += __shfl_down_sync(0xFFFFFFFFu, s1, o);
            q0 += __shfl_down_sync(0xFFFFFFFFu, q0, o);
            q1 += __shfl_down_sync(0xFFFFFFFFu, q1, o);
        }
        if (lane < 4) {
            redS[w][nt * 8 + 2 * t4] = s0;
            redS[w][nt * 8 + 2 * t4 + 1] = s1;
            redQ[w][nt * 8 + 2 * t4] = q0;
            redQ[w][nt * 8 + 2 * t4 + 1] = q1;
        }
    }
    __syncthreads();
    if (tid < 64) {
        int hh = tid >> 5, lc = tid & 31;
        float s = redS[hh * 4 + 0][lc] + redS[hh * 4 + 1][lc]
                + redS[hh * 4 + 2][lc] + redS[hh * 4 + 3][lc];
        float q = redQ[hh * 4 + 0][lc] + redQ[hh * 4 + 1][lc]
                + redQ[hh * 4 + 2][lc] + redQ[hh * 4 + 3][lc];
        atomicAdd(&statsOut[tid], s);
        atomicAdd(&statsOut[64 + tid], q);
    }
}

// ---------------------------------------------------------------------------
// K_final: out = x + relu(BN(t2))
// ---------------------------------------------------------------------------
__global__ __launch_bounds__(256) void k_final(const float* __restrict__ x,
                                               const float* __restrict__ t2,
                                               const float* __restrict__ statsIn,
                                               const float* __restrict__ gamma,
                                               const float* __restrict__ beta,
                                               float* __restrict__ out, int N) {
    __shared__ float SC[64];
    __shared__ float SH[64];
    int tid = threadIdx.x;
    if (tid < 64) {
        float invN = 1.0f / (float)N;
        float mean = statsIn[tid] * invN;
        float var  = statsIn[64 + tid] * invN - mean * mean;
        float sc = gamma[tid] * rsqrtf(var + 1e-5f);
        SC[tid] = sc;
        SH[tid] = beta[tid] - mean * sc;
    }
    __syncthreads();
    int n4 = N * 16;
    for (int i = blockIdx.x * 256 + tid; i < n4; i += gridDim.x * 256) {
        int c = (i & 15) * 4;
        float4 v = ((const float4*)t2)[i];
        float4 xv = ((const float4*)x)[i];
        float4 o;
        o.x = xv.x + fmaxf(fmaf(v.x, SC[c + 0], SH[c + 0]), 0.f);
        o.y = xv.y + fmaxf(fmaf(v.y, SC[c + 1], SH[c + 1]), 0.f);
        o.z = xv.z + fmaxf(fmaf(v.z, SC[c + 2], SH[c + 2]), 0.f);
        o.w = xv.w + fmaxf(fmaf(v.w, SC[c + 3], SH[c + 3]), 0.f);
        ((float4*)out)[i] = o;
    }
}

// ---------------------------------------------------------------------------
extern "C" void kernel_launch(void* const* d_in, const int* in_sizes, int n_in,
                              void* d_out, int out_size) {
    const float* x    = (const float*)d_in[0];
    const int*   ei   = (const int*)d_in[1];
    const float* eps  = (const float*)d_in[2];
    const float* W1   = (const float*)d_in[3];
    const float* b1   = (const float*)d_in[4];
    const float* g1   = (const float*)d_in[5];
    const float* beta1= (const float*)d_in[6];
    const float* W2   = (const float*)d_in[7];
    const float* b2   = (const float*)d_in[8];
    const float* gh   = (const float*)d_in[9];
    const float* betah= (const float*)d_in[10];
    float* out = (float*)d_out;

    int N = in_sizes[0] / D;
    int E = in_sizes[1] / 2;
    if (N > MAXN) N = MAXN;
    if (E > MAXE) E = MAXE;

    float* agg;   cudaGetSymbolAddress((void**)&agg, g_agg);
    float* t1;    cudaGetSymbolAddress((void**)&t1, g_t1);
    float* stats; cudaGetSymbolAddress((void**)&stats, g_stats);

    int prepThreads = (N * 16 > E) ? N * 16 : E;
    int nScanBlocks = (N + SCAN_BLK - 1) / SCAN_BLK;   // 98 <= 148: resident

    k_prep<<<(prepThreads + 255) / 256, 256>>>(x, ei, N, E);
    k_scan<<<nScanBlocks, SCAN_BLK>>>(N);
    k_fill<<<(E + 255) / 256, 256>>>(ei, E);
    k_agg<<<(N + 31) / 32, 256>>>(x, eps, agg, N);

    int gemmBlocks = (N + 63) / 64;
    k_gemm_hmma<<<gemmBlocks, 256>>>(agg, W1, b1, t1, stats,
                                     nullptr, nullptr, nullptr, N, 0);
    k_gemm_hmma<<<gemmBlocks, 256>>>(t1, W2, b2, agg, stats + 128,
                                     stats, g1, beta1, N, 1);

    k_final<<<(N * 16 + 255) / 256, 256>>>(x, agg, stats + 128, gh, betah, out, N);
}